// round 12
// baseline (speedup 1.0000x reference)
#include <cuda_runtime.h>
#include <cuda_fp16.h>
#include <cstdint>

#define N_TOK 16384
#define DIM   1024
#define ODIM  1024
#define NEXP  8

#define TM 128
#define TN 128
#define KC 32
#define NC (DIM / KC)          // 32 k-chunks
#define NSTAGE 4

// dynamic smem layout (GEMM)
#define SM_TOKS  0             // int[128]
#define SM_W     512           // float[128]
#define SM_SLOT  1024          // int[128]
#define SM_BIAS  1536          // float[128]
#define SM_TILES 2048
#define STAGE_BYTES 16384      // {A, B} x 8KB
#define SMEM_BYTES (SM_TILES + NSTAGE * STAGE_BYTES)   // 67584 -> 2 CTA/SM

#define GATE_BLOCKS  (N_TOK / 8)                       // 2048
#define CONVW_BLOCKS (NEXP * (DIM / 64) * (ODIM / 32)) // 4096

// ---- scratch ----
__device__ int     g_count[NEXP];
__device__ int     g_list[NEXP][N_TOK];
__device__ float   g_w[NEXP][N_TOK];
__device__ int     g_slot[NEXP][N_TOK];
__device__ __half  g_partial[2][N_TOK][ODIM];       // fp16 partials
__device__ __half  g_xh[N_TOK][DIM];                // fp16(x)
__device__ __half  g_wt[NEXP][ODIM][DIM];           // fp16(W^T): [e][n][k]

// ===================== helpers =====================
__device__ __forceinline__ uint32_t smem_u32(const void* p) {
    uint32_t a;
    asm("{ .reg .u64 t; cvta.to.shared.u64 t, %1; cvt.u32.u64 %0, t; }"
        : "=r"(a) : "l"(p));
    return a;
}

#define CP_ASYNC16(dst, src) \
    asm volatile("cp.async.cg.shared.global [%0], [%1], 16;" \
                 :: "r"(dst), "l"(src))
#define CP_COMMIT()  asm volatile("cp.async.commit_group;")
#define CP_WAIT2()   asm volatile("cp.async.wait_group 2;")

#define LDSM_X4(r, addr) \
    asm volatile("ldmatrix.sync.aligned.m8n8.x4.shared.b16 {%0,%1,%2,%3}, [%4];" \
                 : "=r"((r)[0]), "=r"((r)[1]), "=r"((r)[2]), "=r"((r)[3]) \
                 : "r"(addr))

// fp16 accumulate, fresh accumulator (c = 0)
#define MMAF16_ZC(d0, d1, a, b) \
    asm volatile("mma.sync.aligned.m16n8k16.row.col.f16.f16.f16.f16 " \
                 "{%0,%1}, {%2,%3,%4,%5}, {%6,%7}, {%8,%9};" \
                 : "=r"(d0), "=r"(d1) \
                 : "r"((a)[0]), "r"((a)[1]), "r"((a)[2]), "r"((a)[3]), \
                   "r"((b)[0]), "r"((b)[1]), "r"(0u), "r"(0u))

// fp16 accumulate, accumulate into d
#define MMAF16_ACC(d0, d1, a, b) \
    asm volatile("mma.sync.aligned.m16n8k16.row.col.f16.f16.f16.f16 " \
                 "{%0,%1}, {%2,%3,%4,%5}, {%6,%7}, {%0,%1};" \
                 : "+r"(d0), "+r"(d1) \
                 : "r"((a)[0]), "r"((a)[1]), "r"((a)[2]), "r"((a)[3]), \
                   "r"((b)[0]), "r"((b)[1]))

// row is a 64B smem row; xor keeps ldmatrix conflict-free
__device__ __forceinline__ uint32_t swz(int row, int chunk) {
    return (uint32_t)(row * 64 + ((chunk ^ ((row >> 1) & 3)) << 4));
}

// ===================== small kernels =====================
__global__ void reset_kernel() {
    if (threadIdx.x < NEXP) g_count[threadIdx.x] = 0;
}

// Fused prep: blocks [0, GATE_BLOCKS) do gate + x->fp16;
//             blocks [GATE_BLOCKS, +CONVW_BLOCKS) transpose/convert W.
__global__ __launch_bounds__(256) void prep_kernel(
    const float* __restrict__ x,
    const float* __restrict__ gw,
    const float* __restrict__ gb,
    const float* __restrict__ ew) {
    __shared__ float sbuf[NEXP * DIM];   // 32 KB (gate); convw uses 8.5 KB of it

    const int tid = threadIdx.x;

    if (blockIdx.x < GATE_BLOCKS) {
        // ---------------- gate ----------------
        float (*gws)[DIM] = (float (*)[DIM])sbuf;
        for (int i = tid; i < DIM * NEXP; i += 256) {
            int d = i >> 3, e = i & 7;
            gws[e][d] = gw[i];
        }
        __syncthreads();

        int warp = (blockIdx.x * 256 + tid) >> 5;
        int lane = tid & 31;
        const float* xr = x + (size_t)warp * DIM;
        __half2* xh2 = (__half2*)&g_xh[warp][0];

        float acc[NEXP];
#pragma unroll
        for (int e = 0; e < NEXP; e++) acc[e] = 0.f;

        for (int it = 0; it < DIM / 128; it++) {
            int d0 = it * 128 + lane * 4;
            float4 v = *(const float4*)(xr + d0);
            xh2[d0 / 2]     = __floats2half2_rn(v.x, v.y);
            xh2[d0 / 2 + 1] = __floats2half2_rn(v.z, v.w);
#pragma unroll
            for (int e = 0; e < NEXP; e++) {
                float4 g = *(const float4*)&gws[e][d0];
                acc[e] += v.x * g.x + v.y * g.y + v.z * g.z + v.w * g.w;
            }
        }
#pragma unroll
        for (int e = 0; e < NEXP; e++)
#pragma unroll
            for (int off = 16; off > 0; off >>= 1)
                acc[e] += __shfl_down_sync(0xffffffffu, acc[e], off);

        if (lane == 0) {
            float logits[NEXP];
            float mx = -1e30f;
#pragma unroll
            for (int e = 0; e < NEXP; e++) {
                logits[e] = acc[e] + gb[e];
                mx = fmaxf(mx, logits[e]);
            }
            float p[NEXP], sum = 0.f;
#pragma unroll
            for (int e = 0; e < NEXP; e++) { p[e] = expf(logits[e] - mx); sum += p[e]; }
            float inv = 1.f / sum;

            int i0 = 0;
#pragma unroll
            for (int e = 1; e < NEXP; e++) if (logits[e] > logits[i0]) i0 = e;
            int i1 = (i0 == 0) ? 1 : 0;
#pragma unroll
            for (int e = 0; e < NEXP; e++)
                if (e != i0 && logits[e] > logits[i1]) i1 = e;

            int pos0 = atomicAdd(&g_count[i0], 1);
            g_list[i0][pos0] = warp; g_w[i0][pos0] = p[i0] * inv; g_slot[i0][pos0] = 0;
            int pos1 = atomicAdd(&g_count[i1], 1);
            g_list[i1][pos1] = warp; g_w[i1][pos1] = p[i1] * inv; g_slot[i1][pos1] = 1;
        }
    } else {
        // ---------------- convw: 64k x 32n tile ----------------
        float (*t)[33] = (float (*)[33])sbuf;     // [64][33] = 8.4 KB
        int b   = blockIdx.x - GATE_BLOCKS;
        int e   = b >> 9;                // 512 tiles per expert
        int rem = b & 511;
        int k0  = (rem >> 5) << 6;       // 16 k-tiles of 64
        int n0  = (rem & 31) << 5;       // 32 n-tiles of 32
        const int tx = tid & 31;
        const int ty = tid >> 5;

        for (int i = ty; i < 64; i += 8)
            t[i][tx] = ew[((size_t)e * DIM + k0 + i) * ODIM + n0 + tx];
        __syncthreads();

        __half2* wt2 = (__half2*)&g_wt[0][0][0];
        for (int i = ty; i < 32; i += 8) {
            __half2 v = __floats2half2_rn(t[2 * tx][i], t[2 * tx + 1][i]);
            size_t o = ((size_t)e * ODIM + n0 + i) * DIM + k0;
            wt2[(o >> 1) + tx] = v;
        }
    }
}

// ====== HMMA grouped GEMM: fp16-accum MMA pairs + fp32 promotion ======
__global__ __launch_bounds__(256, 2) void moe_mma_kernel(const float* __restrict__ eb)
{
    const int e   = blockIdx.z;
    const int cnt = g_count[e];
    const int m0  = blockIdx.y * TM;
    if (m0 >= cnt) return;
    const int n0  = blockIdx.x * TN;

    extern __shared__ char smem[];
    const uint32_t sb = smem_u32(smem);
    int*   toks_s = (int*)(smem + SM_TOKS);
    float* w_s    = (float*)(smem + SM_W);
    int*   slot_s = (int*)(smem + SM_SLOT);
    float* bias_s = (float*)(smem + SM_BIAS);

    const int tid = threadIdx.x;
    const int wid = tid >> 5;
    const int lid = tid & 31;
    const int warp_m = wid & 3;      // 4 M-groups of 32
    const int warp_n = wid >> 2;     // 2 N-groups of 64

    if (tid < TM) {
        int idx = m0 + tid;
        int src = (idx < cnt) ? idx : m0;
        toks_s[tid] = g_list[e][src];
        w_s[tid]    = g_w[e][src];
        slot_s[tid] = g_slot[e][src];
        bias_s[tid] = eb[e * ODIM + n0 + tid];
    }
    __syncthreads();

    const char* xB = (const char*)&g_xh[0][0];
    const char* wB = (const char*)&g_wt[0][0][0] + (((size_t)e * ODIM + n0) * DIM) * 2;

    // per-thread load slots: row r (0..127), half h (0/1): chunks 2h, 2h+1
    const int lr = tid >> 1;
    const int lh = tid & 1;
    const int ltok = toks_s[lr];
    const uint32_t so0 = swz(lr, 2 * lh);
    const uint32_t so1 = swz(lr, 2 * lh + 1);
    const size_t aoff = ((size_t)ltok * DIM) * 2 + (size_t)lh * 32;
    const size_t boff = ((size_t)lr * DIM) * 2 + (size_t)lh * 32;

#define LOAD_STAGE(kc, s) do {                                              \
        uint32_t b_ = sb + SM_TILES + (s) * STAGE_BYTES;                    \
        size_t kb_ = (size_t)(kc) * (KC * 2);                               \
        const char* pa = xB + aoff + kb_;                                   \
        const char* pb = wB + boff + kb_;                                   \
        CP_ASYNC16(b_ + so0,         pa);                                   \
        CP_ASYNC16(b_ + so1,         pa + 16);                              \
        CP_ASYNC16(b_ + 8192 + so0,  pb);                                   \
        CP_ASYNC16(b_ + 8192 + so1,  pb + 16);                              \
    } while (0)

    LOAD_STAGE(0, 0); CP_COMMIT();
    LOAD_STAGE(1, 1); CP_COMMIT();
    LOAD_STAGE(2, 2); CP_COMMIT();

    float acc[2][8][4];
#pragma unroll
    for (int i = 0; i < 2; i++)
#pragma unroll
        for (int j = 0; j < 8; j++)
#pragma unroll
            for (int q = 0; q < 4; q++) acc[i][j][q] = 0.f;

    const int a_row = (lid & 15);
    const int a_ch  = (lid >> 4);
    const int b_nr  = ((lid >> 4) << 3) + (lid & 7);
    const int b_ch  = ((lid >> 3) & 1);

    for (int kc = 0; kc < NC; kc++) {
        CP_WAIT2();
        __syncthreads();
        if (kc + 3 < NC) LOAD_STAGE(kc + 3, (kc + 3) & 3);
        CP_COMMIT();

        uint32_t base = sb + SM_TILES + (kc & 3) * STAGE_BYTES;

        // load fragments for BOTH ks halves of this chunk
        uint32_t av[2][2][4];            // [ks][mt]
        uint32_t bv[2][4][4];            // [ks][bt]
#pragma unroll
        for (int ks = 0; ks < 2; ks++) {
#pragma unroll
            for (int mt = 0; mt < 2; mt++) {
                int row = warp_m * 32 + mt * 16 + a_row;
                LDSM_X4(av[ks][mt], base + swz(row, ks * 2 + a_ch));
            }
#pragma unroll
            for (int bt = 0; bt < 4; bt++) {
                int n = warp_n * 64 + bt * 16 + b_nr;
                LDSM_X4(bv[ks][bt], base + 8192 + swz(n, ks * 2 + b_ch));
            }
        }

        // fp16-accum pair per tile, then promote to fp32 accumulators
#pragma unroll
        for (int mt = 0; mt < 2; mt++)
#pragma unroll
            for (int nt = 0; nt < 8; nt++) {
                uint32_t d0, d1;
                MMAF16_ZC(d0, d1, av[0][mt], (&bv[0][nt >> 1][(nt & 1) * 2]));
                MMAF16_ACC(d0, d1, av[1][mt], (&bv[1][nt >> 1][(nt & 1) * 2]));
                float2 lo = __half22float2(*(__half2*)&d0);
                float2 hi = __half22float2(*(__half2*)&d1);
                acc[mt][nt][0] += lo.x;
                acc[mt][nt][1] += lo.y;
                acc[mt][nt][2] += hi.x;
                acc[mt][nt][3] += hi.y;
            }
    }

    // epilogue: fp16( w * (acc + bias) ) -> partial[slot][tok]
#pragma unroll
    for (int mt = 0; mt < 2; mt++) {
        int r0 = warp_m * 32 + mt * 16 + (lid >> 2);
        int r1 = r0 + 8;
        bool live0 = (m0 + r0) < cnt;
        bool live1 = (m0 + r1) < cnt;
        int   t0 = toks_s[r0],  t1 = toks_s[r1];
        float w0 = w_s[r0],     w1 = w_s[r1];
        int   s0 = slot_s[r0],  s1 = slot_s[r1];
        __half* p0 = &g_partial[s0][t0][n0];
        __half* p1 = &g_partial[s1][t1][n0];
#pragma unroll
        for (int nt = 0; nt < 8; nt++) {
            int col = warp_n * 64 + nt * 8 + (lid & 3) * 2;
            float b0 = bias_s[col], b1 = bias_s[col + 1];
            if (live0)
                *(__half2*)(p0 + col) =
                    __floats2half2_rn(w0 * (acc[mt][nt][0] + b0),
                                      w0 * (acc[mt][nt][1] + b1));
            if (live1)
                *(__half2*)(p1 + col) =
                    __floats2half2_rn(w1 * (acc[mt][nt][2] + b0),
                                      w1 * (acc[mt][nt][3] + b1));
        }
    }
}

// out = fp32(partial0) + fp32(partial1); 8 elems / thread
__global__ void combine_kernel(float* __restrict__ out) {
    size_t i = (size_t)blockIdx.x * blockDim.x + threadIdx.x;
    size_t total = (size_t)N_TOK * ODIM / 8;
    if (i >= total) return;
    const uint4* p0 = (const uint4*)g_partial[0];
    const uint4* p1 = (const uint4*)g_partial[1];
    uint4 a = p0[i], b = p1[i];
    float4 o0, o1;
    {
        float2 x0 = __half22float2(*(__half2*)&a.x), y0 = __half22float2(*(__half2*)&b.x);
        float2 x1 = __half22float2(*(__half2*)&a.y), y1 = __half22float2(*(__half2*)&b.y);
        o0 = make_float4(x0.x + y0.x, x0.y + y0.y, x1.x + y1.x, x1.y + y1.y);
        float2 x2 = __half22float2(*(__half2*)&a.z), y2 = __half22float2(*(__half2*)&b.z);
        float2 x3 = __half22float2(*(__half2*)&a.w), y3 = __half22float2(*(__half2*)&b.w);
        o1 = make_float4(x2.x + y2.x, x2.y + y2.y, x3.x + y3.x, x3.y + y3.y);
    }
    ((float4*)out)[i * 2]     = o0;
    ((float4*)out)[i * 2 + 1] = o1;
}

// ===================== launch =====================
extern "C" void kernel_launch(void* const* d_in, const int* in_sizes, int n_in,
                              void* d_out, int out_size) {
    const float* x  = (const float*)d_in[0];
    const float* gw = (const float*)d_in[1];
    const float* gb = (const float*)d_in[2];
    const float* ew = (const float*)d_in[3];
    const float* eb = (const float*)d_in[4];
    float* out = (float*)d_out;

    reset_kernel<<<1, 32>>>();
    prep_kernel<<<GATE_BLOCKS + CONVW_BLOCKS, 256>>>(x, gw, gb, ew);

    static bool attr_set = false;
    if (!attr_set) {
        cudaFuncSetAttribute(moe_mma_kernel,
                             cudaFuncAttributeMaxDynamicSharedMemorySize, SMEM_BYTES);
        attr_set = true;
    }
    dim3 grid(ODIM / TN, N_TOK / TM, NEXP);
    moe_mma_kernel<<<grid, 256, SMEM_BYTES>>>(eb);

    combine_kernel<<<(N_TOK * ODIM / 8 + 255) / 256, 256>>>(out);
}

// round 13
// speedup vs baseline: 1.0361x; 1.0361x over previous
#include <cuda_runtime.h>
#include <cuda_fp16.h>
#include <cstdint>

#define N_TOK 16384
#define DIM   1024
#define ODIM  1024
#define NEXP  8

#define TM 128
#define TN 128
#define KC 32
#define NC (DIM / KC)          // 32 k-chunks
#define NSTAGE 4

// dynamic smem layout (GEMM)
#define SM_TOKS  0             // int[128]
#define SM_W     512           // float[128]
#define SM_SLOT  1024          // int[128]
#define SM_BIAS  1536          // float[128]
#define SM_TILES 2048
#define STAGE_BYTES 16384      // {A, B} x 8KB
#define SMEM_BYTES (SM_TILES + NSTAGE * STAGE_BYTES)   // 67584 -> 2 CTA/SM

#define GATE_BLOCKS  (N_TOK / 8)                       // 2048
#define CONVW_BLOCKS (NEXP * (DIM / 64) * (ODIM / 32)) // 4096

// ---- scratch (g_count zero-initialized; combine re-zeroes each run) ----
__device__ int     g_count[NEXP];
__device__ int     g_list[NEXP][N_TOK];
__device__ float   g_w[NEXP][N_TOK];
__device__ int     g_slot[NEXP][N_TOK];
__device__ __half  g_partial[2][N_TOK][ODIM];       // fp16 partials
__device__ __half  g_xh[N_TOK][DIM];                // fp16(x)
__device__ __half  g_wt[NEXP][ODIM][DIM];           // fp16(W^T): [e][n][k]

// ===================== helpers =====================
__device__ __forceinline__ uint32_t smem_u32(const void* p) {
    uint32_t a;
    asm("{ .reg .u64 t; cvta.to.shared.u64 t, %1; cvt.u32.u64 %0, t; }"
        : "=r"(a) : "l"(p));
    return a;
}

#define CP_ASYNC16(dst, src) \
    asm volatile("cp.async.cg.shared.global [%0], [%1], 16;" \
                 :: "r"(dst), "l"(src))
#define CP_COMMIT()  asm volatile("cp.async.commit_group;")
#define CP_WAIT2()   asm volatile("cp.async.wait_group 2;")

#define LDSM_X4(r, addr) \
    asm volatile("ldmatrix.sync.aligned.m8n8.x4.shared.b16 {%0,%1,%2,%3}, [%4];" \
                 : "=r"((r)[0]), "=r"((r)[1]), "=r"((r)[2]), "=r"((r)[3]) \
                 : "r"(addr))

// fp16 inputs, fp32 accumulate
#define MMAF32(d, a, b) \
    asm volatile("mma.sync.aligned.m16n8k16.row.col.f32.f16.f16.f32 " \
                 "{%0,%1,%2,%3}, {%4,%5,%6,%7}, {%8,%9}, {%0,%1,%2,%3};" \
                 : "+f"((d)[0]), "+f"((d)[1]), "+f"((d)[2]), "+f"((d)[3]) \
                 : "r"((a)[0]), "r"((a)[1]), "r"((a)[2]), "r"((a)[3]), \
                   "r"((b)[0]), "r"((b)[1]))

// row is a 64B smem row; xor keeps ldmatrix conflict-free
__device__ __forceinline__ uint32_t swz(int row, int chunk) {
    return (uint32_t)(row * 64 + ((chunk ^ ((row >> 1) & 3)) << 4));
}

// ===================== prep: gate + convw fused =====================
// blocks [0, GATE_BLOCKS): gate + x->fp16 (gw read direct from global;
//   each thread reads a CONTIGUOUS 128B of gw per iter -> coalesced,
//   L1-resident after first wave; no smem, no barrier)
// blocks [GATE_BLOCKS, +CONVW_BLOCKS): transpose/convert W (smem tile)
__global__ __launch_bounds__(256) void prep_kernel(
    const float* __restrict__ x,
    const float* __restrict__ gw,
    const float* __restrict__ gb,
    const float* __restrict__ ew) {
    __shared__ float t[64][33];        // 8.4 KB, used by convw branch only

    const int tid = threadIdx.x;

    if (blockIdx.x < GATE_BLOCKS) {
        // ---------------- gate ----------------
        int warp = (blockIdx.x * 256 + tid) >> 5;
        int lane = tid & 31;
        const float* xr = x + (size_t)warp * DIM;
        __half2* xh2 = (__half2*)&g_xh[warp][0];

        float acc[NEXP];
#pragma unroll
        for (int e = 0; e < NEXP; e++) acc[e] = 0.f;

        for (int it = 0; it < DIM / 128; it++) {
            int d0 = it * 128 + lane * 4;          // 4 consecutive d rows
            float4 v = *(const float4*)(xr + d0);
            xh2[d0 / 2]     = __floats2half2_rn(v.x, v.y);
            xh2[d0 / 2 + 1] = __floats2half2_rn(v.z, v.w);
            const float* g = gw + (size_t)d0 * NEXP;   // 128B contiguous/thread
            float xv[4] = {v.x, v.y, v.z, v.w};
#pragma unroll
            for (int r = 0; r < 4; r++) {
                float4 ga = *(const float4*)(g + r * NEXP);
                float4 gc = *(const float4*)(g + r * NEXP + 4);
                acc[0] += xv[r] * ga.x;  acc[1] += xv[r] * ga.y;
                acc[2] += xv[r] * ga.z;  acc[3] += xv[r] * ga.w;
                acc[4] += xv[r] * gc.x;  acc[5] += xv[r] * gc.y;
                acc[6] += xv[r] * gc.z;  acc[7] += xv[r] * gc.w;
            }
        }
#pragma unroll
        for (int e = 0; e < NEXP; e++)
#pragma unroll
            for (int off = 16; off > 0; off >>= 1)
                acc[e] += __shfl_down_sync(0xffffffffu, acc[e], off);

        if (lane == 0) {
            float logits[NEXP];
            float mx = -1e30f;
#pragma unroll
            for (int e = 0; e < NEXP; e++) {
                logits[e] = acc[e] + gb[e];
                mx = fmaxf(mx, logits[e]);
            }
            float p[NEXP], sum = 0.f;
#pragma unroll
            for (int e = 0; e < NEXP; e++) { p[e] = expf(logits[e] - mx); sum += p[e]; }
            float inv = 1.f / sum;

            int i0 = 0;
#pragma unroll
            for (int e = 1; e < NEXP; e++) if (logits[e] > logits[i0]) i0 = e;
            int i1 = (i0 == 0) ? 1 : 0;
#pragma unroll
            for (int e = 0; e < NEXP; e++)
                if (e != i0 && logits[e] > logits[i1]) i1 = e;

            int pos0 = atomicAdd(&g_count[i0], 1);
            g_list[i0][pos0] = warp; g_w[i0][pos0] = p[i0] * inv; g_slot[i0][pos0] = 0;
            int pos1 = atomicAdd(&g_count[i1], 1);
            g_list[i1][pos1] = warp; g_w[i1][pos1] = p[i1] * inv; g_slot[i1][pos1] = 1;
        }
    } else {
        // ---------------- convw: 64k x 32n tile ----------------
        int b   = blockIdx.x - GATE_BLOCKS;
        int e   = b >> 9;                // 512 tiles per expert
        int rem = b & 511;
        int k0  = (rem >> 5) << 6;       // 16 k-tiles of 64
        int n0  = (rem & 31) << 5;       // 32 n-tiles of 32
        const int tx = tid & 31;
        const int ty = tid >> 5;

        for (int i = ty; i < 64; i += 8)
            t[i][tx] = ew[((size_t)e * DIM + k0 + i) * ODIM + n0 + tx];
        __syncthreads();

        __half2* wt2 = (__half2*)&g_wt[0][0][0];
        for (int i = ty; i < 32; i += 8) {
            __half2 v = __floats2half2_rn(t[2 * tx][i], t[2 * tx + 1][i]);
            size_t o = ((size_t)e * ODIM + n0 + i) * DIM + k0;
            wt2[(o >> 1) + tx] = v;
        }
    }
}

// ===================== HMMA grouped GEMM (single-pass fp16, f32 accum) ======
__global__ __launch_bounds__(256, 2) void moe_mma_kernel(const float* __restrict__ eb)
{
    const int e   = blockIdx.z;
    const int cnt = g_count[e];
    const int m0  = blockIdx.y * TM;
    if (m0 >= cnt) return;
    const int n0  = blockIdx.x * TN;

    extern __shared__ char smem[];
    const uint32_t sb = smem_u32(smem);
    int*   toks_s = (int*)(smem + SM_TOKS);
    float* w_s    = (float*)(smem + SM_W);
    int*   slot_s = (int*)(smem + SM_SLOT);
    float* bias_s = (float*)(smem + SM_BIAS);

    const int tid = threadIdx.x;
    const int wid = tid >> 5;
    const int lid = tid & 31;
    const int warp_m = wid & 3;      // 4 M-groups of 32
    const int warp_n = wid >> 2;     // 2 N-groups of 64

    if (tid < TM) {
        int idx = m0 + tid;
        int src = (idx < cnt) ? idx : m0;
        toks_s[tid] = g_list[e][src];
        w_s[tid]    = g_w[e][src];
        slot_s[tid] = g_slot[e][src];
        bias_s[tid] = eb[e * ODIM + n0 + tid];
    }
    __syncthreads();

    const char* xB = (const char*)&g_xh[0][0];
    const char* wB = (const char*)&g_wt[0][0][0] + (((size_t)e * ODIM + n0) * DIM) * 2;

    // per-thread load slots: row r (0..127), half h (0/1): chunks 2h, 2h+1
    const int lr = tid >> 1;
    const int lh = tid & 1;
    const int ltok = toks_s[lr];
    const uint32_t so0 = swz(lr, 2 * lh);
    const uint32_t so1 = swz(lr, 2 * lh + 1);
    const size_t aoff = ((size_t)ltok * DIM) * 2 + (size_t)lh * 32;
    const size_t boff = ((size_t)lr * DIM) * 2 + (size_t)lh * 32;

#define LOAD_STAGE(kc, s) do {                                              \
        uint32_t b_ = sb + SM_TILES + (s) * STAGE_BYTES;                    \
        size_t kb_ = (size_t)(kc) * (KC * 2);                               \
        const char* pa = xB + aoff + kb_;                                   \
        const char* pb = wB + boff + kb_;                                   \
        CP_ASYNC16(b_ + so0,         pa);                                   \
        CP_ASYNC16(b_ + so1,         pa + 16);                              \
        CP_ASYNC16(b_ + 8192 + so0,  pb);                                   \
        CP_ASYNC16(b_ + 8192 + so1,  pb + 16);                              \
    } while (0)

    LOAD_STAGE(0, 0); CP_COMMIT();
    LOAD_STAGE(1, 1); CP_COMMIT();
    LOAD_STAGE(2, 2); CP_COMMIT();

    float acc[2][8][4];
#pragma unroll
    for (int i = 0; i < 2; i++)
#pragma unroll
        for (int j = 0; j < 8; j++)
#pragma unroll
            for (int q = 0; q < 4; q++) acc[i][j][q] = 0.f;

    const int a_row = (lid & 15);
    const int a_ch  = (lid >> 4);
    const int b_nr  = ((lid >> 4) << 3) + (lid & 7);
    const int b_ch  = ((lid >> 3) & 1);

    for (int kc = 0; kc < NC; kc++) {
        CP_WAIT2();
        __syncthreads();
        if (kc + 3 < NC) LOAD_STAGE(kc + 3, (kc + 3) & 3);
        CP_COMMIT();

        uint32_t base = sb + SM_TILES + (kc & 3) * STAGE_BYTES;

#pragma unroll
        for (int ks = 0; ks < 2; ks++) {
            uint32_t av[2][4];
#pragma unroll
            for (int mt = 0; mt < 2; mt++) {
                int row = warp_m * 32 + mt * 16 + a_row;
                LDSM_X4(av[mt], base + swz(row, ks * 2 + a_ch));
            }
            uint32_t bv[4][4];
#pragma unroll
            for (int bt = 0; bt < 4; bt++) {
                int n = warp_n * 64 + bt * 16 + b_nr;
                LDSM_X4(bv[bt], base + 8192 + swz(n, ks * 2 + b_ch));
            }
#pragma unroll
            for (int mt = 0; mt < 2; mt++)
#pragma unroll
                for (int nt = 0; nt < 8; nt++)
                    MMAF32(acc[mt][nt], av[mt], (&bv[nt >> 1][(nt & 1) * 2]));
        }
    }

    // epilogue: fp16( w * (acc + bias) ) -> partial[slot][tok]
#pragma unroll
    for (int mt = 0; mt < 2; mt++) {
        int r0 = warp_m * 32 + mt * 16 + (lid >> 2);
        int r1 = r0 + 8;
        bool live0 = (m0 + r0) < cnt;
        bool live1 = (m0 + r1) < cnt;
        int   t0 = toks_s[r0],  t1 = toks_s[r1];
        float w0 = w_s[r0],     w1 = w_s[r1];
        int   s0 = slot_s[r0],  s1 = slot_s[r1];
        __half* p0 = &g_partial[s0][t0][n0];
        __half* p1 = &g_partial[s1][t1][n0];
#pragma unroll
        for (int nt = 0; nt < 8; nt++) {
            int col = warp_n * 64 + nt * 8 + (lid & 3) * 2;
            float b0 = bias_s[col], b1 = bias_s[col + 1];
            if (live0)
                *(__half2*)(p0 + col) =
                    __floats2half2_rn(w0 * (acc[mt][nt][0] + b0),
                                      w0 * (acc[mt][nt][1] + b1));
            if (live1)
                *(__half2*)(p1 + col) =
                    __floats2half2_rn(w1 * (acc[mt][nt][2] + b0),
                                      w1 * (acc[mt][nt][3] + b1));
        }
    }
}

// out = fp32(partial0) + fp32(partial1); also re-zeroes g_count for the
// next graph replay (static zero-init covers the first run).
__global__ void combine_kernel(float* __restrict__ out) {
    size_t i = (size_t)blockIdx.x * blockDim.x + threadIdx.x;
    size_t total = (size_t)N_TOK * ODIM / 8;
    if (blockIdx.x == 0 && threadIdx.x < NEXP) g_count[threadIdx.x] = 0;
    if (i >= total) return;
    const uint4* p0 = (const uint4*)g_partial[0];
    const uint4* p1 = (const uint4*)g_partial[1];
    uint4 a = p0[i], b = p1[i];
    float4 o0, o1;
    {
        float2 x0 = __half22float2(*(__half2*)&a.x), y0 = __half22float2(*(__half2*)&b.x);
        float2 x1 = __half22float2(*(__half2*)&a.y), y1 = __half22float2(*(__half2*)&b.y);
        o0 = make_float4(x0.x + y0.x, x0.y + y0.y, x1.x + y1.x, x1.y + y1.y);
        float2 x2 = __half22float2(*(__half2*)&a.z), y2 = __half22float2(*(__half2*)&b.z);
        float2 x3 = __half22float2(*(__half2*)&a.w), y3 = __half22float2(*(__half2*)&b.w);
        o1 = make_float4(x2.x + y2.x, x2.y + y2.y, x3.x + y3.x, x3.y + y3.y);
    }
    ((float4*)out)[i * 2]     = o0;
    ((float4*)out)[i * 2 + 1] = o1;
}

// ===================== launch =====================
extern "C" void kernel_launch(void* const* d_in, const int* in_sizes, int n_in,
                              void* d_out, int out_size) {
    const float* x  = (const float*)d_in[0];
    const float* gw = (const float*)d_in[1];
    const float* gb = (const float*)d_in[2];
    const float* ew = (const float*)d_in[3];
    const float* eb = (const float*)d_in[4];
    float* out = (float*)d_out;

    prep_kernel<<<GATE_BLOCKS + CONVW_BLOCKS, 256>>>(x, gw, gb, ew);

    static bool attr_set = false;
    if (!attr_set) {
        cudaFuncSetAttribute(moe_mma_kernel,
                             cudaFuncAttributeMaxDynamicSharedMemorySize, SMEM_BYTES);
        attr_set = true;
    }
    dim3 grid(ODIM / TN, N_TOK / TM, NEXP);
    moe_mma_kernel<<<grid, 256, SMEM_BYTES>>>(eb);

    combine_kernel<<<(N_TOK * ODIM / 8 + 255) / 256, 256>>>(out);
}

// round 14
// speedup vs baseline: 1.2635x; 1.2195x over previous
#include <cuda_runtime.h>
#include <cuda_fp16.h>
#include <cstdint>

#define N_TOK 16384
#define DIM   1024
#define ODIM  1024
#define NEXP  8

#define TM 128
#define TN 128
#define KC 32
#define NC (DIM / KC)          // 32 k-chunks
#define NSTAGE 4

// dynamic smem layout (GEMM)
#define SM_TOKS  0             // int[128]
#define SM_W     512           // float[128]
#define SM_SLOT  1024          // int[128]
#define SM_BIAS  1536          // float[128]
#define SM_TILES 2048
#define STAGE_BYTES 16384      // {A, B} x 8KB
#define SMEM_BYTES (SM_TILES + NSTAGE * STAGE_BYTES)   // 67584 -> 2 CTA/SM

#define GATE_BLOCKS  (N_TOK / 8)                       // 2048
#define CONVW_BLOCKS (NEXP * (DIM / 64) * (ODIM / 32)) // 4096

// ---- scratch (g_count zero-initialized; combine re-zeroes each run) ----
__device__ int     g_count[NEXP];
__device__ int     g_list[NEXP][N_TOK];
__device__ float   g_w[NEXP][N_TOK];
__device__ int     g_slot[NEXP][N_TOK];
__device__ __half  g_partial[2][N_TOK][ODIM];       // fp16 partials
__device__ __half  g_xh[N_TOK][DIM];                // fp16(x)
__device__ __half  g_wt[NEXP][ODIM][DIM];           // fp16(W^T): [e][n][k]

// ===================== helpers =====================
__device__ __forceinline__ uint32_t smem_u32(const void* p) {
    uint32_t a;
    asm("{ .reg .u64 t; cvta.to.shared.u64 t, %1; cvt.u32.u64 %0, t; }"
        : "=r"(a) : "l"(p));
    return a;
}

#define CP_ASYNC16(dst, src) \
    asm volatile("cp.async.cg.shared.global [%0], [%1], 16;" \
                 :: "r"(dst), "l"(src))
#define CP_COMMIT()  asm volatile("cp.async.commit_group;")
#define CP_WAIT2()   asm volatile("cp.async.wait_group 2;")

#define LDSM_X4(r, addr) \
    asm volatile("ldmatrix.sync.aligned.m8n8.x4.shared.b16 {%0,%1,%2,%3}, [%4];" \
                 : "=r"((r)[0]), "=r"((r)[1]), "=r"((r)[2]), "=r"((r)[3]) \
                 : "r"(addr))

// fp16 inputs, fp32 accumulate
#define MMAF32(d, a, b) \
    asm volatile("mma.sync.aligned.m16n8k16.row.col.f32.f16.f16.f32 " \
                 "{%0,%1,%2,%3}, {%4,%5,%6,%7}, {%8,%9}, {%0,%1,%2,%3};" \
                 : "+f"((d)[0]), "+f"((d)[1]), "+f"((d)[2]), "+f"((d)[3]) \
                 : "r"((a)[0]), "r"((a)[1]), "r"((a)[2]), "r"((a)[3]), \
                   "r"((b)[0]), "r"((b)[1]))

// row is a 64B smem row; xor keeps ldmatrix conflict-free
__device__ __forceinline__ uint32_t swz(int row, int chunk) {
    return (uint32_t)(row * 64 + ((chunk ^ ((row >> 1) & 3)) << 4));
}

// ===================== prep: gate + convw fused =====================
// blocks [0, GATE_BLOCKS): gate + x->fp16. gw staged TRANSPOSED in smem
//   (LDS.128 conflict-free); all 8 x-loads batched up front (MLP=8).
// blocks [GATE_BLOCKS, +CONVW_BLOCKS): transpose/convert W.
__global__ __launch_bounds__(256) void prep_kernel(
    const float* __restrict__ x,
    const float* __restrict__ gw,
    const float* __restrict__ gb,
    const float* __restrict__ ew) {
    __shared__ float sbuf[NEXP * DIM];   // 32 KB gate; convw reuses 8.4 KB

    const int tid = threadIdx.x;

    if (blockIdx.x < GATE_BLOCKS) {
        // ---------------- gate ----------------
        float (*gws)[DIM] = (float (*)[DIM])sbuf;
        for (int i = tid; i < DIM * NEXP; i += 256) {
            int d = i >> 3, e = i & 7;
            gws[e][d] = gw[i];
        }
        __syncthreads();

        int warp = (blockIdx.x * 256 + tid) >> 5;
        int lane = tid & 31;
        const float* xr = x + (size_t)warp * DIM;
        __half2* xh2 = (__half2*)&g_xh[warp][0];

        // batch ALL x loads first (MLP=8 -> DRAM latency hidden)
        float4 xv[8];
#pragma unroll
        for (int it = 0; it < 8; it++)
            xv[it] = *(const float4*)(xr + it * 128 + lane * 4);
#pragma unroll
        for (int it = 0; it < 8; it++) {
            int d0 = it * 128 + lane * 4;
            xh2[d0 / 2]     = __floats2half2_rn(xv[it].x, xv[it].y);
            xh2[d0 / 2 + 1] = __floats2half2_rn(xv[it].z, xv[it].w);
        }

        float acc[NEXP];
#pragma unroll
        for (int e = 0; e < NEXP; e++) acc[e] = 0.f;
#pragma unroll
        for (int it = 0; it < 8; it++) {
            int d0 = it * 128 + lane * 4;
#pragma unroll
            for (int e = 0; e < NEXP; e++) {
                float4 g = *(const float4*)&gws[e][d0];
                acc[e] += xv[it].x * g.x + xv[it].y * g.y +
                          xv[it].z * g.z + xv[it].w * g.w;
            }
        }
#pragma unroll
        for (int e = 0; e < NEXP; e++)
#pragma unroll
            for (int off = 16; off > 0; off >>= 1)
                acc[e] += __shfl_down_sync(0xffffffffu, acc[e], off);

        if (lane == 0) {
            float logits[NEXP];
            float mx = -1e30f;
#pragma unroll
            for (int e = 0; e < NEXP; e++) {
                logits[e] = acc[e] + gb[e];
                mx = fmaxf(mx, logits[e]);
            }
            float p[NEXP], sum = 0.f;
#pragma unroll
            for (int e = 0; e < NEXP; e++) { p[e] = expf(logits[e] - mx); sum += p[e]; }
            float inv = 1.f / sum;

            int i0 = 0;
#pragma unroll
            for (int e = 1; e < NEXP; e++) if (logits[e] > logits[i0]) i0 = e;
            int i1 = (i0 == 0) ? 1 : 0;
#pragma unroll
            for (int e = 0; e < NEXP; e++)
                if (e != i0 && logits[e] > logits[i1]) i1 = e;

            int pos0 = atomicAdd(&g_count[i0], 1);
            g_list[i0][pos0] = warp; g_w[i0][pos0] = p[i0] * inv; g_slot[i0][pos0] = 0;
            int pos1 = atomicAdd(&g_count[i1], 1);
            g_list[i1][pos1] = warp; g_w[i1][pos1] = p[i1] * inv; g_slot[i1][pos1] = 1;
        }
    } else {
        // ---------------- convw: 64k x 32n tile ----------------
        float (*t)[33] = (float (*)[33])sbuf;     // [64][33] = 8.4 KB
        int b   = blockIdx.x - GATE_BLOCKS;
        int e   = b >> 9;                // 512 tiles per expert
        int rem = b & 511;
        int k0  = (rem >> 5) << 6;       // 16 k-tiles of 64
        int n0  = (rem & 31) << 5;       // 32 n-tiles of 32
        const int tx = tid & 31;
        const int ty = tid >> 5;

        for (int i = ty; i < 64; i += 8)
            t[i][tx] = ew[((size_t)e * DIM + k0 + i) * ODIM + n0 + tx];
        __syncthreads();

        __half2* wt2 = (__half2*)&g_wt[0][0][0];
        for (int i = ty; i < 32; i += 8) {
            __half2 v = __floats2half2_rn(t[2 * tx][i], t[2 * tx + 1][i]);
            size_t o = ((size_t)e * ODIM + n0 + i) * DIM + k0;
            wt2[(o >> 1) + tx] = v;
        }
    }
}

// ===================== HMMA grouped GEMM (single-pass fp16, f32 accum) ======
__global__ __launch_bounds__(256, 2) void moe_mma_kernel(const float* __restrict__ eb)
{
    const int e   = blockIdx.z;
    const int cnt = g_count[e];
    const int m0  = blockIdx.y * TM;
    if (m0 >= cnt) return;
    const int n0  = blockIdx.x * TN;

    extern __shared__ char smem[];
    const uint32_t sb = smem_u32(smem);
    int*   toks_s = (int*)(smem + SM_TOKS);
    float* w_s    = (float*)(smem + SM_W);
    int*   slot_s = (int*)(smem + SM_SLOT);
    float* bias_s = (float*)(smem + SM_BIAS);

    const int tid = threadIdx.x;
    const int wid = tid >> 5;
    const int lid = tid & 31;
    const int warp_m = wid & 3;      // 4 M-groups of 32
    const int warp_n = wid >> 2;     // 2 N-groups of 64

    if (tid < TM) {
        int idx = m0 + tid;
        int src = (idx < cnt) ? idx : m0;
        toks_s[tid] = g_list[e][src];
        w_s[tid]    = g_w[e][src];
        slot_s[tid] = g_slot[e][src];
        bias_s[tid] = eb[e * ODIM + n0 + tid];
    }
    __syncthreads();

    const char* xB = (const char*)&g_xh[0][0];
    const char* wB = (const char*)&g_wt[0][0][0] + (((size_t)e * ODIM + n0) * DIM) * 2;

    // per-thread load slots: row r (0..127), half h (0/1): chunks 2h, 2h+1
    const int lr = tid >> 1;
    const int lh = tid & 1;
    const int ltok = toks_s[lr];
    const uint32_t so0 = swz(lr, 2 * lh);
    const uint32_t so1 = swz(lr, 2 * lh + 1);
    const size_t aoff = ((size_t)ltok * DIM) * 2 + (size_t)lh * 32;
    const size_t boff = ((size_t)lr * DIM) * 2 + (size_t)lh * 32;

#define LOAD_STAGE(kc, s) do {                                              \
        uint32_t b_ = sb + SM_TILES + (s) * STAGE_BYTES;                    \
        size_t kb_ = (size_t)(kc) * (KC * 2);                               \
        const char* pa = xB + aoff + kb_;                                   \
        const char* pb = wB + boff + kb_;                                   \
        CP_ASYNC16(b_ + so0,         pa);                                   \
        CP_ASYNC16(b_ + so1,         pa + 16);                              \
        CP_ASYNC16(b_ + 8192 + so0,  pb);                                   \
        CP_ASYNC16(b_ + 8192 + so1,  pb + 16);                              \
    } while (0)

    LOAD_STAGE(0, 0); CP_COMMIT();
    LOAD_STAGE(1, 1); CP_COMMIT();
    LOAD_STAGE(2, 2); CP_COMMIT();

    float acc[2][8][4];
#pragma unroll
    for (int i = 0; i < 2; i++)
#pragma unroll
        for (int j = 0; j < 8; j++)
#pragma unroll
            for (int q = 0; q < 4; q++) acc[i][j][q] = 0.f;

    const int a_row = (lid & 15);
    const int a_ch  = (lid >> 4);
    const int b_nr  = ((lid >> 4) << 3) + (lid & 7);
    const int b_ch  = ((lid >> 3) & 1);

    for (int kc = 0; kc < NC; kc++) {
        CP_WAIT2();
        __syncthreads();
        if (kc + 3 < NC) LOAD_STAGE(kc + 3, (kc + 3) & 3);
        CP_COMMIT();

        uint32_t base = sb + SM_TILES + (kc & 3) * STAGE_BYTES;

#pragma unroll
        for (int ks = 0; ks < 2; ks++) {
            uint32_t av[2][4];
#pragma unroll
            for (int mt = 0; mt < 2; mt++) {
                int row = warp_m * 32 + mt * 16 + a_row;
                LDSM_X4(av[mt], base + swz(row, ks * 2 + a_ch));
            }
            uint32_t bv[4][4];
#pragma unroll
            for (int bt = 0; bt < 4; bt++) {
                int n = warp_n * 64 + bt * 16 + b_nr;
                LDSM_X4(bv[bt], base + 8192 + swz(n, ks * 2 + b_ch));
            }
#pragma unroll
            for (int mt = 0; mt < 2; mt++)
#pragma unroll
                for (int nt = 0; nt < 8; nt++)
                    MMAF32(acc[mt][nt], av[mt], (&bv[nt >> 1][(nt & 1) * 2]));
        }
    }

    // epilogue: fp16( w * (acc + bias) ) -> partial[slot][tok]
#pragma unroll
    for (int mt = 0; mt < 2; mt++) {
        int r0 = warp_m * 32 + mt * 16 + (lid >> 2);
        int r1 = r0 + 8;
        bool live0 = (m0 + r0) < cnt;
        bool live1 = (m0 + r1) < cnt;
        int   t0 = toks_s[r0],  t1 = toks_s[r1];
        float w0 = w_s[r0],     w1 = w_s[r1];
        int   s0 = slot_s[r0],  s1 = slot_s[r1];
        __half* p0 = &g_partial[s0][t0][n0];
        __half* p1 = &g_partial[s1][t1][n0];
#pragma unroll
        for (int nt = 0; nt < 8; nt++) {
            int col = warp_n * 64 + nt * 8 + (lid & 3) * 2;
            float b0 = bias_s[col], b1 = bias_s[col + 1];
            if (live0)
                *(__half2*)(p0 + col) =
                    __floats2half2_rn(w0 * (acc[mt][nt][0] + b0),
                                      w0 * (acc[mt][nt][1] + b1));
            if (live1)
                *(__half2*)(p1 + col) =
                    __floats2half2_rn(w1 * (acc[mt][nt][2] + b0),
                                      w1 * (acc[mt][nt][3] + b1));
        }
    }
}

// out = fp32(partial0) + fp32(partial1); re-zeroes g_count for next replay
__global__ void combine_kernel(float* __restrict__ out) {
    size_t i = (size_t)blockIdx.x * blockDim.x + threadIdx.x;
    size_t total = (size_t)N_TOK * ODIM / 8;
    if (blockIdx.x == 0 && threadIdx.x < NEXP) g_count[threadIdx.x] = 0;
    if (i >= total) return;
    const uint4* p0 = (const uint4*)g_partial[0];
    const uint4* p1 = (const uint4*)g_partial[1];
    uint4 a = p0[i], b = p1[i];
    float4 o0, o1;
    {
        float2 x0 = __half22float2(*(__half2*)&a.x), y0 = __half22float2(*(__half2*)&b.x);
        float2 x1 = __half22float2(*(__half2*)&a.y), y1 = __half22float2(*(__half2*)&b.y);
        o0 = make_float4(x0.x + y0.x, x0.y + y0.y, x1.x + y1.x, x1.y + y1.y);
        float2 x2 = __half22float2(*(__half2*)&a.z), y2 = __half22float2(*(__half2*)&b.z);
        float2 x3 = __half22float2(*(__half2*)&a.w), y3 = __half22float2(*(__half2*)&b.w);
        o1 = make_float4(x2.x + y2.x, x2.y + y2.y, x3.x + y3.x, x3.y + y3.y);
    }
    ((float4*)out)[i * 2]     = o0;
    ((float4*)out)[i * 2 + 1] = o1;
}

// ===================== launch =====================
extern "C" void kernel_launch(void* const* d_in, const int* in_sizes, int n_in,
                              void* d_out, int out_size) {
    const float* x  = (const float*)d_in[0];
    const float* gw = (const float*)d_in[1];
    const float* gb = (const float*)d_in[2];
    const float* ew = (const float*)d_in[3];
    const float* eb = (const float*)d_in[4];
    float* out = (float*)d_out;

    prep_kernel<<<GATE_BLOCKS + CONVW_BLOCKS, 256>>>(x, gw, gb, ew);

    static bool attr_set = false;
    if (!attr_set) {
        cudaFuncSetAttribute(moe_mma_kernel,
                             cudaFuncAttributeMaxDynamicSharedMemorySize, SMEM_BYTES);
        attr_set = true;
    }
    dim3 grid(ODIM / TN, N_TOK / TM, NEXP);
    moe_mma_kernel<<<grid, 256, SMEM_BYTES>>>(eb);

    combine_kernel<<<(N_TOK * ODIM / 8 + 255) / 256, 256>>>(out);
}